// round 2
// baseline (speedup 1.0000x reference)
#include <cuda_runtime.h>
#include <cuda_bf16.h>

// OrdinalRegressionLoss: mean over B x 4 of
//   max(x,0) - x*[j < target] + log1p(exp(-|x|))
// B = 8,388,608 rows, 4 thresholds (fp32), targets int32 (harness narrows int64).
// HBM-bound streaming reduction: 160 MiB read -> floor ~26 us.

#define NBLOCKS 1184          // 148 SMs * 8 blocks
#define NTHREADS 256
#define MAX_PARTIALS 2048

__device__ float g_partials[MAX_PARTIALS];

__device__ __forceinline__ float bce_term(float x, float y) {
    float ax = fabsf(x);
    // log1p(exp(-ax)), ax >= 0 so exp(-ax) in (0,1]: fast-math is accurate enough (<1e-6 abs)
    float sp = __logf(1.0f + __expf(-ax));
    return fmaxf(x, 0.0f) - x * y + sp;
}

__global__ void __launch_bounds__(NTHREADS, 8)
ordinal_loss_partial(const float4* __restrict__ logits4,
                     const int* __restrict__ targets,
                     int nrows) {
    float acc = 0.0f;
    int stride = gridDim.x * blockDim.x;
    for (int i = blockIdx.x * blockDim.x + threadIdx.x; i < nrows; i += stride) {
        float4 l = logits4[i];          // one row = one coalesced 16B load
        int t = targets[i];             // int32, coalesced 4B load
        acc += bce_term(l.x, (float)(0 < t));
        acc += bce_term(l.y, (float)(1 < t));
        acc += bce_term(l.z, (float)(2 < t));
        acc += bce_term(l.w, (float)(3 < t));
    }

    // warp reduce
    #pragma unroll
    for (int o = 16; o > 0; o >>= 1)
        acc += __shfl_down_sync(0xffffffffu, acc, o);

    __shared__ float ws[NTHREADS / 32];
    int lane = threadIdx.x & 31;
    int wid  = threadIdx.x >> 5;
    if (lane == 0) ws[wid] = acc;
    __syncthreads();

    if (wid == 0) {
        float v = (lane < NTHREADS / 32) ? ws[lane] : 0.0f;
        #pragma unroll
        for (int o = 4; o > 0; o >>= 1)
            v += __shfl_down_sync(0xffffffffu, v, o);
        if (lane == 0) g_partials[blockIdx.x] = v;
    }
}

__global__ void __launch_bounds__(256)
ordinal_loss_final(float* __restrict__ out, int nparts, float inv_total) {
    float acc = 0.0f;
    for (int i = threadIdx.x; i < nparts; i += 256)
        acc += g_partials[i];

    #pragma unroll
    for (int o = 16; o > 0; o >>= 1)
        acc += __shfl_down_sync(0xffffffffu, acc, o);

    __shared__ float ws[8];
    int lane = threadIdx.x & 31;
    int wid  = threadIdx.x >> 5;
    if (lane == 0) ws[wid] = acc;
    __syncthreads();

    if (wid == 0) {
        float v = (lane < 8) ? ws[lane] : 0.0f;
        #pragma unroll
        for (int o = 4; o > 0; o >>= 1)
            v += __shfl_down_sync(0xffffffffu, v, o);
        if (lane == 0) out[0] = v * inv_total;
    }
}

extern "C" void kernel_launch(void* const* d_in, const int* in_sizes, int n_in,
                              void* d_out, int out_size) {
    const float4* logits4 = (const float4*)d_in[0];   // (B,4) fp32
    const int* targets    = (const int*)d_in[1];      // (B,) int32 on device
    float* out = (float*)d_out;

    int nrows = in_sizes[1];                          // B
    float inv_total = 1.0f / ((float)nrows * 4.0f);

    ordinal_loss_partial<<<NBLOCKS, NTHREADS>>>(logits4, targets, nrows);
    ordinal_loss_final<<<1, 256>>>(out, NBLOCKS, inv_total);
}

// round 3
// speedup vs baseline: 1.0667x; 1.0667x over previous
#include <cuda_runtime.h>
#include <cuda_bf16.h>

// OrdinalRegressionLoss: mean over B x 4 of
//   max(x,0) - x*[j < target] + log1p(exp(-|x|))
// B = 8,388,608 rows, logits fp32 (B,4), targets int32 (B,).
// 160 MiB streamed once -> HBM-bound. Single fused kernel with
// threadfence-reduction tail (no second launch).

#define NBLOCKS 592           // 148 SMs * 4 blocks, one wave
#define NTHREADS 256

__device__ float g_partials[NBLOCKS];
__device__ unsigned int g_count = 0;   // reset by last block each run -> graph-replay safe

__device__ __forceinline__ float bce_term(float x, float y) {
    float ax = fabsf(x);
    // log1p(exp(-ax)), ax >= 0 so exp(-ax) in (0,1]
    float sp = __logf(1.0f + __expf(-ax));
    return fmaxf(x, 0.0f) - x * y + sp;
}

__device__ __forceinline__ float row_loss(float4 l, int t) {
    float s = bce_term(l.x, (float)(0 < t));
    s += bce_term(l.y, (float)(1 < t));
    s += bce_term(l.z, (float)(2 < t));
    s += bce_term(l.w, (float)(3 < t));
    return s;
}

__device__ __forceinline__ float block_reduce(float acc, float* ws) {
    #pragma unroll
    for (int o = 16; o > 0; o >>= 1)
        acc += __shfl_down_sync(0xffffffffu, acc, o);
    int lane = threadIdx.x & 31;
    int wid  = threadIdx.x >> 5;
    if (lane == 0) ws[wid] = acc;
    __syncthreads();
    float v = 0.0f;
    if (wid == 0) {
        v = (lane < NTHREADS / 32) ? ws[lane] : 0.0f;
        #pragma unroll
        for (int o = 4; o > 0; o >>= 1)
            v += __shfl_down_sync(0xffffffffu, v, o);
    }
    return v;   // valid in (wid==0, lane==0)
}

__global__ void __launch_bounds__(NTHREADS, 4)
ordinal_loss_fused(const float4* __restrict__ logits4,
                   const int* __restrict__ targets,
                   int nrows, float inv_total, float* __restrict__ out) {
    __shared__ float ws[NTHREADS / 32];
    __shared__ bool is_last;

    float acc = 0.0f;
    int ngroups = nrows >> 2;                 // 4 rows per group
    int stride = gridDim.x * blockDim.x;
    const int4* targets4 = (const int4*)targets;

    for (int g = blockIdx.x * blockDim.x + threadIdx.x; g < ngroups; g += stride) {
        // 5 independent 16B loads in flight per iteration (MLP)
        float4 l0 = __ldcs(logits4 + g * 4 + 0);
        float4 l1 = __ldcs(logits4 + g * 4 + 1);
        float4 l2 = __ldcs(logits4 + g * 4 + 2);
        float4 l3 = __ldcs(logits4 + g * 4 + 3);
        int4   t4 = __ldcs(targets4 + g);
        acc += row_loss(l0, t4.x);
        acc += row_loss(l1, t4.y);
        acc += row_loss(l2, t4.z);
        acc += row_loss(l3, t4.w);
    }
    // tail rows (nrows % 4) — handled by low global threads
    int rem_base = ngroups << 2;
    int r = rem_base + blockIdx.x * blockDim.x + threadIdx.x;
    if (r < nrows)
        acc += row_loss(__ldcs(logits4 + r), __ldcs(targets + r));

    float bsum = block_reduce(acc, ws);
    if (threadIdx.x == 0) {
        g_partials[blockIdx.x] = bsum;
        __threadfence();
        unsigned int old = atomicAdd(&g_count, 1u);
        is_last = (old == gridDim.x - 1);
    }
    __syncthreads();

    if (is_last) {
        // last block sums all partials (L2-resident) and writes the scalar
        float a = 0.0f;
        for (int i = threadIdx.x; i < (int)gridDim.x; i += NTHREADS)
            a += g_partials[i];
        __syncthreads();          // ws reuse hazard
        float total = block_reduce(a, ws);
        if (threadIdx.x == 0) {
            out[0] = total * inv_total;
            g_count = 0;          // reset for next graph replay
        }
    }
}

extern "C" void kernel_launch(void* const* d_in, const int* in_sizes, int n_in,
                              void* d_out, int out_size) {
    const float4* logits4 = (const float4*)d_in[0];   // (B,4) fp32
    const int* targets    = (const int*)d_in[1];      // (B,) int32 on device
    float* out = (float*)d_out;

    int nrows = in_sizes[1];                          // B
    float inv_total = 1.0f / ((float)nrows * 4.0f);

    ordinal_loss_fused<<<NBLOCKS, NTHREADS>>>(logits4, targets, nrows, inv_total, out);
}